// round 13
// baseline (speedup 1.0000x reference)
#include <cuda_runtime.h>
#include <cuda_bf16.h>
#include <cstdint>

// Problem constants (fixed by the reference)
#define KFEAT   128
#define NTHETA  32
#define NSTEP   32
#define TILE_N  256      // nodes per CTA (4 x 64-node rounds)
#define RN      64       // nodes per round
#define NROUND  4
#define NTHREADS 256
#define MAXG    128      // NUM_GRAPHS (fixed by the reference)

// ---- SMEM layout (bytes, dynamic) ----
// bf16 tiles at 256B row pitch, XOR swizzle on 16B seg index: s ^= (row & 7)
#define SA_HI     0          // 64 x 128 bf16 (16 KB)
#define SA_LO     16384
#define SB_HI     32768      // 32 x 128 bf16 (8 KB)
#define SB_LO     40960
#define SM_BSH    49152      // 256 int
#define SM_TOTAL  50176

// Global scratch: per-graph diff array [g][s][th] (zeroed each launch)
__device__ float g_diff[MAXG * NSTEP * NTHETA];

__device__ __forceinline__ float fast_sigmoid(float z) {
    float e = __expf(-z);
    return __fdividef(1.0f, 1.0f + e);
}

union BU { __nv_bfloat162 h; unsigned u; };

__device__ __forceinline__ unsigned pack_hi(float a, float b, float& ra, float& rb) {
    BU u; u.h = __floats2bfloat162_rn(a, b);
    float2 f = __bfloat1622float2(u.h);
    ra = a - f.x; rb = b - f.y;
    return u.u;
}
__device__ __forceinline__ unsigned pack_lo(float a, float b) {
    BU u; u.h = __floats2bfloat162_rn(a, b); return u.u;
}

__device__ __forceinline__ void ldsm4(unsigned* r, uint32_t addr) {
    asm volatile("ldmatrix.sync.aligned.m8n8.x4.shared.b16 {%0,%1,%2,%3}, [%4];"
        : "=r"(r[0]), "=r"(r[1]), "=r"(r[2]), "=r"(r[3]) : "r"(addr));
}

static __device__ __forceinline__ uint32_t smem_u32(const void* p) {
    uint32_t a;
    asm("{ .reg .u64 t; cvta.to.shared.u64 t, %1; cvt.u32.u64 %0, t; }" : "=r"(a) : "l"(p));
    return a;
}

// D(m16n8) += A(m16k16,row) * B(k16n8,col) ; bf16 in, f32 acc
#define MMA(d0, d1, d2, d3, A, B0, B1) \
    asm volatile("mma.sync.aligned.m16n8k16.row.col.f32.bf16.bf16.f32 " \
        "{%0,%1,%2,%3}, {%4,%5,%6,%7}, {%8,%9}, {%0,%1,%2,%3};" \
        : "+f"(d0), "+f"(d1), "+f"(d2), "+f"(d3) \
        : "r"((A)[0]), "r"((A)[1]), "r"((A)[2]), "r"((A)[3]), "r"(B0), "r"(B1))

__global__ void zero_diff_kernel(int n) {
    int i = blockIdx.x * blockDim.x + threadIdx.x;
    if (i < n) g_diff[i] = 0.0f;
}

__global__ void __launch_bounds__(NTHREADS, 3)
ect_hmma_kernel(const float* __restrict__ x,
                const void*  __restrict__ batch_raw,
                const float* __restrict__ v,
                int n_nodes)
{
    extern __shared__ char smem[];
    const uint32_t sbase = smem_u32(smem);
    const int tid  = threadIdx.x;
    const int warp = tid >> 5;
    const int lane = tid & 31;
    const int g    = lane >> 2;     // fragment row group
    const int t4   = lane & 3;      // fragment col group
    const int w4   = warp & 3;      // row-slice of the 64-node round
    const int half = warp >> 2;     // theta half: 0 -> th 0-15, 1 -> th 16-31
    const int tile_base = blockIdx.x * TILE_N;

    int* bsh = (int*)(smem + SM_BSH);

    const float Rr = 1.1f, STEP = 2.2f / 31.0f, INV_STEP = 31.0f / 2.2f;
    const float SCALE = 100.0f;
    const float ZSTEP = SCALE * STEP;   // z-spacing between samples = 7.0968

    // batch dtype: int64 (JAX x64) vs int32 (default)
    const unsigned* bw = (const unsigned*)batch_raw;
    const bool is64 = (bw[n_nodes - 1] == 0u);

    // ---- Stage v -> B_hi/B_lo bf16 (32 rows x 256B): 512 segs, 2/thread ----
    #pragma unroll
    for (int it = 0; it < 2; ++it) {
        int idx = it * NTHREADS + tid;
        int row = idx >> 4, s = idx & 15;
        const float4* p = (const float4*)(v + row * KFEAT + s * 8);
        float4 fa = p[0], fb = p[1];
        float r0, r1, r2, r3, r4, r5, r6, r7;
        uint4 H, L;
        H.x = pack_hi(fa.x, fa.y, r0, r1); H.y = pack_hi(fa.z, fa.w, r2, r3);
        H.z = pack_hi(fb.x, fb.y, r4, r5); H.w = pack_hi(fb.z, fb.w, r6, r7);
        L.x = pack_lo(r0, r1); L.y = pack_lo(r2, r3);
        L.z = pack_lo(r4, r5); L.w = pack_lo(r6, r7);
        int sw = row * 256 + (s ^ (row & 7)) * 16;
        *(uint4*)(smem + SB_HI + sw) = H;
        *(uint4*)(smem + SB_LO + sw) = L;
    }
    // batch labels for this tile
    {
        int n = tile_base + tid;
        int b = 0;
        if (n < n_nodes)
            b = is64 ? (int)((const long long*)batch_raw)[n] : ((const int*)batch_raw)[n];
        bsh[tid] = b;
    }

    // ldmatrix per-lane row bases; swizzled seg index per k-chunk:
    //   addr = rowbase + (((kc*2 + h16) ^ (row&7)) << 4)
    const int l15 = lane & 15, h16 = lane >> 4;
    const int m7 = l15 & 7;
    const uint32_t rowA = sbase + (uint32_t)((w4 * 16 + l15) * 256);
    const uint32_t rowB = sbase + (uint32_t)((half * 16 + l15) * 256);

    float acc[NROUND][8];
    #pragma unroll
    for (int i = 0; i < NROUND; ++i)
        #pragma unroll
        for (int j = 0; j < 8; ++j) acc[i][j] = 0.0f;

    // ---- Four rounds: stage 64 nodes to bf16 hi/lo, HMMA accumulate ----
    #pragma unroll 1
    for (int rd = 0; rd < NROUND; ++rd) {
        __syncthreads();                  // prev round ldsm done / init staging done
        #pragma unroll
        for (int it = 0; it < 4; ++it) {  // 1024 segs, 4/thread
            int idx = it * NTHREADS + tid;
            int row = idx >> 4, s = idx & 15;
            int n = tile_base + rd * RN + row;
            if (n >= n_nodes) n = n_nodes - 1;
            const float4* p = (const float4*)(x + (size_t)n * KFEAT + s * 8);
            float4 fa = p[0], fb = p[1];
            float r0, r1, r2, r3, r4, r5, r6, r7;
            uint4 H, L;
            H.x = pack_hi(fa.x, fa.y, r0, r1); H.y = pack_hi(fa.z, fa.w, r2, r3);
            H.z = pack_hi(fb.x, fb.y, r4, r5); H.w = pack_hi(fb.z, fb.w, r6, r7);
            L.x = pack_lo(r0, r1); L.y = pack_lo(r2, r3);
            L.z = pack_lo(r4, r5); L.w = pack_lo(r6, r7);
            int sw = row * 256 + (s ^ (row & 7)) * 16;
            *(uint4*)(smem + SA_HI + sw) = H;
            *(uint4*)(smem + SA_LO + sw) = L;
        }
        __syncthreads();

        #pragma unroll
        for (int kc = 0; kc < 8; ++kc) {
            const uint32_t so = (uint32_t)(((kc * 2 + h16) ^ m7) << 4);
            unsigned ah[4], al[4], bh[4], bl[4];
            ldsm4(ah, rowA + SA_HI + so);
            ldsm4(al, rowA + SA_LO + so);
            ldsm4(bh, rowB + SB_HI + so);
            ldsm4(bl, rowB + SB_LO + so);
            #pragma unroll
            for (int nb = 0; nb < 2; ++nb) {
                unsigned b0h = bh[nb], b1h = bh[nb + 2];
                unsigned b0l = bl[nb], b1l = bl[nb + 2];
                int j0 = nb * 4;
                MMA(acc[rd][j0], acc[rd][j0+1], acc[rd][j0+2], acc[rd][j0+3], ah, b0h, b1h);
                MMA(acc[rd][j0], acc[rd][j0+1], acc[rd][j0+2], acc[rd][j0+3], ah, b0l, b1l);
                MMA(acc[rd][j0], acc[rd][j0+1], acc[rd][j0+2], acc[rd][j0+3], al, b0h, b1h);
            }
        }
    }

    // ---- Epilogue: scatter single-sample diff contributions to g_diff ----
    // acc[rd][nb*4+c] = nh[node][theta]
    //   node  = rd*64 + w4*16 + g + (c>=2 ? 8 : 0)
    //   theta = half*16 + nb*8 + 2*t4 + (c&1)
    // Contributions per (node,th):
    //   s* <  0  : +1 at d[g][0][th]
    //   0<=s*<=31: +sig at d[g][s*][th], +(1-sig) at d[g][s*+1][th] (drop if s*=31)
    //   s* > 31  : nothing
    // atomicAdd with unused result compiles to REDG (fire-and-forget).
    const int node_base = w4 * 16 + g;
    #pragma unroll
    for (int rd = 0; rd < NROUND; ++rd) {
        #pragma unroll
        for (int q = 0; q < 8; ++q) {
            const int nb = q >> 2, c = q & 3;
            const int node = rd * RN + node_base + ((c >= 2) ? 8 : 0);
            const int th = half * 16 + nb * 8 + 2 * t4 + (c & 1);
            if (tile_base + node < n_nodes) {
                const int gg = bsh[node];
                float nh = acc[rd][q];
                float a  = (nh + Rr) * INV_STEP;   // crossing position in s-units
                int ss   = __float2int_rn(a);      // the single transition sample
                float* gd = g_diff + gg * (NSTEP * NTHETA) + th;
                if (ss < 0) {
                    atomicAdd(gd, 1.0f);
                } else if (ss <= 31) {
                    float sg = fast_sigmoid(ZSTEP * ((float)ss - a));
                    atomicAdd(gd + ss * NTHETA, sg);
                    if (ss < 31)
                        atomicAdd(gd + (ss + 1) * NTHETA, 1.0f - sg);
                }
            }
        }
    }
}

// Count nodes with label `key` boundary via lower_bound on the sorted batch.
__device__ int lower_bound_batch(const void* b, int n, long long key, bool is64) {
    int lo = 0, hi = n;
    while (lo < hi) {
        int mid = (lo + hi) >> 1;
        long long v = is64 ? ((const long long*)b)[mid]
                           : (long long)((const int*)b)[mid];
        if (v < key) lo = mid + 1; else hi = mid;
    }
    return lo;
}

// Prefix-sum g_diff over s, subtract cnt*cs[s], write out. One block per graph.
__global__ void finish_kernel(const void* __restrict__ batch_raw,
                              float* __restrict__ out, int n_nodes) {
    const int gg = blockIdx.x, t = threadIdx.x;
    __shared__ int c0, c1;
    const unsigned* bw = (const unsigned*)batch_raw;
    const bool is64 = (bw[n_nodes - 1] == 0u);
    if (t == 0) c0 = lower_bound_batch(batch_raw, n_nodes, gg, is64);
    if (t == 1 || blockDim.x == 1) c1 = lower_bound_batch(batch_raw, n_nodes, gg + 1, is64);
    __syncthreads();
    const float cnt = (float)(c1 - c0);
    const float Rr = 1.1f, STEP = 2.2f / 31.0f, SCALE = 100.0f;
    const float* gd = g_diff + gg * (NSTEP * NTHETA) + t;
    float* og = out + (size_t)gg * (NSTEP * NTHETA) + t;
    float run = 0.0f;
    #pragma unroll
    for (int s = 0; s < NSTEP; ++s) {
        run += gd[s * NTHETA];
        float lin = fmaf((float)s, STEP, -Rr);
        float zc  = SCALE * (lin - Rr);
        float cs  = (zc > -25.0f) ? fast_sigmoid(zc) : 0.0f;
        og[s * NTHETA] = run - cnt * cs;
    }
}

extern "C" void kernel_launch(void* const* d_in, const int* in_sizes, int n_in,
                              void* d_out, int out_size) {
    int xi = 0; long long best = -1;
    for (int i = 0; i < n_in; ++i)
        if ((long long)in_sizes[i] > best) { best = in_sizes[i]; xi = i; }
    const float* x = (const float*)d_in[xi];
    int n_nodes = (int)(best / KFEAT);
    const void* batch = nullptr;
    const float* v = nullptr;
    for (int i = 0; i < n_in; ++i) {
        if (i == xi) continue;
        if (in_sizes[i] == NTHETA * KFEAT) v = (const float*)d_in[i];
        else if (in_sizes[i] == n_nodes)   batch = d_in[i];
    }
    float* out = (float*)d_out;
    int ng = out_size / (NSTEP * NTHETA);   // 128

    static bool attr_set = false;
    if (!attr_set) {
        cudaFuncSetAttribute(ect_hmma_kernel,
                             cudaFuncAttributeMaxDynamicSharedMemorySize, SM_TOTAL);
        attr_set = true;
    }
    int dn = ng * NSTEP * NTHETA;
    zero_diff_kernel<<<(dn + 255) / 256, 256>>>(dn);
    int tiles = (n_nodes + TILE_N - 1) / TILE_N;
    ect_hmma_kernel<<<tiles, NTHREADS, SM_TOTAL>>>(x, batch, v, n_nodes);
    finish_kernel<<<ng, NTHETA>>>(batch, out, n_nodes);
}

// round 14
// speedup vs baseline: 1.0377x; 1.0377x over previous
#include <cuda_runtime.h>
#include <cuda_bf16.h>
#include <cstdint>

// Problem constants (fixed by the reference)
#define KFEAT   128
#define NTHETA  32
#define NSTEP   32
#define TILE_N  256      // nodes per CTA (4 x 64-node rounds)
#define RN      64       // nodes per round
#define NROUND  4
#define NTHREADS 256
#define HP      33       // diff-array pitch (bank spread)

// ---- SMEM layout (bytes, dynamic) ----
// bf16 tiles at 256B row pitch, XOR swizzle on 16B seg index: s ^= (row & 7)
#define SA_HI     0          // 64 x 128 bf16 (16 KB)
#define SA_LO     16384
#define SB_HI     32768      // 32 x 128 bf16 (8 KB)
#define SB_LO     40960
#define SM_DIFF   49152      // 2 slots x 32*33 floats (8448 B)
#define SM_BSH    57600      // 256 int
#define SM_CS     58624      // 32 float
#define SM_CNT    58752      // 2 int
#define SM_TOTAL  58760

__device__ __forceinline__ float fast_sigmoid(float z) {
    float e = __expf(-z);
    return __fdividef(1.0f, 1.0f + e);
}

union BU { __nv_bfloat162 h; unsigned u; };

__device__ __forceinline__ unsigned pack_hi(float a, float b, float& ra, float& rb) {
    BU u; u.h = __floats2bfloat162_rn(a, b);
    float2 f = __bfloat1622float2(u.h);
    ra = a - f.x; rb = b - f.y;
    return u.u;
}
__device__ __forceinline__ unsigned pack_lo(float a, float b) {
    BU u; u.h = __floats2bfloat162_rn(a, b); return u.u;
}

__device__ __forceinline__ void ldsm4(unsigned* r, uint32_t addr) {
    asm volatile("ldmatrix.sync.aligned.m8n8.x4.shared.b16 {%0,%1,%2,%3}, [%4];"
        : "=r"(r[0]), "=r"(r[1]), "=r"(r[2]), "=r"(r[3]) : "r"(addr));
}

static __device__ __forceinline__ uint32_t smem_u32(const void* p) {
    uint32_t a;
    asm("{ .reg .u64 t; cvta.to.shared.u64 t, %1; cvt.u32.u64 %0, t; }" : "=r"(a) : "l"(p));
    return a;
}

// D(m16n8) += A(m16k16,row) * B(k16n8,col) ; bf16 in, f32 acc
#define MMA(d0, d1, d2, d3, A, B0, B1) \
    asm volatile("mma.sync.aligned.m16n8k16.row.col.f32.bf16.bf16.f32 " \
        "{%0,%1,%2,%3}, {%4,%5,%6,%7}, {%8,%9}, {%0,%1,%2,%3};" \
        : "+f"(d0), "+f"(d1), "+f"(d2), "+f"(d3) \
        : "r"((A)[0]), "r"((A)[1]), "r"((A)[2]), "r"((A)[3]), "r"(B0), "r"(B1))

__global__ void zero_kernel(float* __restrict__ out, int n) {
    int i = blockIdx.x * blockDim.x + threadIdx.x;
    if (i < n) out[i] = 0.0f;
}

__global__ void __launch_bounds__(NTHREADS, 3)
ect_hmma_kernel(const float* __restrict__ x,
                const void*  __restrict__ batch_raw,
                const float* __restrict__ v,
                float* __restrict__ out,
                int n_nodes)
{
    extern __shared__ char smem[];
    const uint32_t sbase = smem_u32(smem);
    const int tid  = threadIdx.x;
    const int warp = tid >> 5;
    const int lane = tid & 31;
    const int g    = lane >> 2;     // fragment row group
    const int t4   = lane & 3;      // fragment col group
    const int w4   = warp & 3;      // row-slice of the 64-node round
    const int half = warp >> 2;     // theta half: 0 -> th 0-15, 1 -> th 16-31
    const int tile_base = blockIdx.x * TILE_N;
    const int valid_n = min(TILE_N, n_nodes - tile_base);

    float* diff  = (float*)(smem + SM_DIFF);   // [2][NSTEP*HP]
    int*   bsh   = (int*)  (smem + SM_BSH);
    float* cs_sh = (float*)(smem + SM_CS);
    int*   cntsh = (int*)  (smem + SM_CNT);

    const float Rr = 1.1f, STEP = 2.2f / 31.0f, INV_STEP = 31.0f / 2.2f;
    const float SCALE = 100.0f;
    const float ZSTEP = SCALE * STEP;   // z-spacing between samples = 7.0968

    // batch dtype: int64 (JAX x64) vs int32 (default)
    const unsigned* bw = (const unsigned*)batch_raw;
    const bool is64 = (bw[n_nodes - 1] == 0u);

    // ---- Stage v -> B_hi/B_lo bf16 (32 rows x 256B): 512 segs, 2/thread ----
    #pragma unroll
    for (int it = 0; it < 2; ++it) {
        int idx = it * NTHREADS + tid;
        int row = idx >> 4, s = idx & 15;
        const float4* p = (const float4*)(v + row * KFEAT + s * 8);
        float4 fa = p[0], fb = p[1];
        float r0, r1, r2, r3, r4, r5, r6, r7;
        uint4 H, L;
        H.x = pack_hi(fa.x, fa.y, r0, r1); H.y = pack_hi(fa.z, fa.w, r2, r3);
        H.z = pack_hi(fb.x, fb.y, r4, r5); H.w = pack_hi(fb.z, fb.w, r6, r7);
        L.x = pack_lo(r0, r1); L.y = pack_lo(r2, r3);
        L.z = pack_lo(r4, r5); L.w = pack_lo(r6, r7);
        int sw = row * 256 + (s ^ (row & 7)) * 16;
        *(uint4*)(smem + SB_HI + sw) = H;
        *(uint4*)(smem + SB_LO + sw) = L;
    }
    // batch labels + pad-sigmoid table
    {
        int n = tile_base + tid;
        int b = 0x7fffffff;
        if (n < n_nodes)
            b = is64 ? (int)((const long long*)batch_raw)[n] : ((const int*)batch_raw)[n];
        bsh[tid] = b;
    }
    if (tid < NSTEP) {
        float lin = fmaf((float)tid, STEP, -Rr);
        float zc  = SCALE * (lin - Rr);
        cs_sh[tid] = (zc > -25.0f) ? fast_sigmoid(zc) : 0.0f;
    }

    // ldmatrix per-lane row bases; swizzled seg index per k-chunk:
    //   addr = rowbase + (((kc*2 + h16) ^ (row&7)) << 4)
    const int l15 = lane & 15, h16 = lane >> 4;
    const int m7 = l15 & 7;
    const uint32_t rowA = sbase + (uint32_t)((w4 * 16 + l15) * 256);
    const uint32_t rowB = sbase + (uint32_t)((half * 16 + l15) * 256);

    float acc[NROUND][8];
    #pragma unroll
    for (int i = 0; i < NROUND; ++i)
        #pragma unroll
        for (int j = 0; j < 8; ++j) acc[i][j] = 0.0f;

    // ---- Four rounds: stage 64 nodes to bf16 hi/lo, HMMA accumulate ----
    #pragma unroll 1
    for (int rd = 0; rd < NROUND; ++rd) {
        __syncthreads();                  // prev round ldsm done / init staging done
        #pragma unroll
        for (int it = 0; it < 4; ++it) {  // 1024 segs, 4/thread
            int idx = it * NTHREADS + tid;
            int row = idx >> 4, s = idx & 15;
            int n = tile_base + rd * RN + row;
            if (n >= n_nodes) n = n_nodes - 1;
            const float4* p = (const float4*)(x + (size_t)n * KFEAT + s * 8);
            float4 fa = p[0], fb = p[1];
            float r0, r1, r2, r3, r4, r5, r6, r7;
            uint4 H, L;
            H.x = pack_hi(fa.x, fa.y, r0, r1); H.y = pack_hi(fa.z, fa.w, r2, r3);
            H.z = pack_hi(fb.x, fb.y, r4, r5); H.w = pack_hi(fb.z, fb.w, r6, r7);
            L.x = pack_lo(r0, r1); L.y = pack_lo(r2, r3);
            L.z = pack_lo(r4, r5); L.w = pack_lo(r6, r7);
            int sw = row * 256 + (s ^ (row & 7)) * 16;
            *(uint4*)(smem + SA_HI + sw) = H;
            *(uint4*)(smem + SA_LO + sw) = L;
        }
        __syncthreads();

        #pragma unroll
        for (int kc = 0; kc < 8; ++kc) {
            const uint32_t so = (uint32_t)(((kc * 2 + h16) ^ m7) << 4);
            unsigned ah[4], al[4], bh[4], bl[4];
            ldsm4(ah, rowA + SA_HI + so);
            ldsm4(al, rowA + SA_LO + so);
            ldsm4(bh, rowB + SB_HI + so);
            ldsm4(bl, rowB + SB_LO + so);
            #pragma unroll
            for (int nb = 0; nb < 2; ++nb) {
                unsigned b0h = bh[nb], b1h = bh[nb + 2];
                unsigned b0l = bl[nb], b1l = bl[nb + 2];
                int j0 = nb * 4;
                MMA(acc[rd][j0], acc[rd][j0+1], acc[rd][j0+2], acc[rd][j0+3], ah, b0h, b1h);
                MMA(acc[rd][j0], acc[rd][j0+1], acc[rd][j0+2], acc[rd][j0+3], ah, b0l, b1l);
                MMA(acc[rd][j0], acc[rd][j0+1], acc[rd][j0+2], acc[rd][j0+3], al, b0h, b1h);
            }
        }
    }

    // Ownership: acc[rd][nb*4+c] = nh[node][theta]
    //   node  = rd*64 + w4*16 + g + (c>=2 ? 8 : 0)
    //   theta = half*16 + nb*8 + 2*t4 + (c&1)
    const int node_base = w4 * 16 + g;

    // Per-thread node labels for the 8 distinct nodes (rd x c-half)
    int lab8[8];
    #pragma unroll
    for (int rd = 0; rd < NROUND; ++rd) {
        lab8[rd * 2 + 0] = bsh[rd * RN + node_base];
        lab8[rd * 2 + 1] = bsh[rd * RN + node_base + 8];
    }

    // ---- Single-pass epilogue: clamped single-sample diff scatter ----
    // ss = clamp(round(a), 0, 31); add sig(ZSTEP*(ss-a)) at d[slot][ss][th]
    // and (1-sig) at d[slot][ss+1][th] (dropped at ss==31). Exact at the
    // clamped boundary sample; error elsewhere <= e^-3.55 per pair.
    // out[g][s][th] = prefix_s(d) - cnt_g_tile * cs[s], atomically merged.
    const int g0   = bsh[0];
    const int gmax = bsh[valid_n - 1];
    #pragma unroll 1
    for (int cb = g0; cb <= gmax; cb += 2) {       // 1 iteration in practice
        __syncthreads();
        for (int i2 = tid; i2 < 2 * NSTEP * HP; i2 += NTHREADS) diff[i2] = 0.0f;
        if (tid < 2) cntsh[tid] = 0;
        __syncthreads();
        if (tid < valid_n) {
            int sl = bsh[tid] - cb;
            if (sl == 0 || sl == 1) atomicAdd(&cntsh[sl], 1);
        }
        #pragma unroll
        for (int rd = 0; rd < NROUND; ++rd) {
            #pragma unroll
            for (int q = 0; q < 8; ++q) {
                const int nb = q >> 2, c = q & 3;
                const int hi8 = (c >= 2) ? 1 : 0;
                const int node = rd * RN + node_base + hi8 * 8;
                const int th = half * 16 + nb * 8 + 2 * t4 + (c & 1);
                const int sl = lab8[rd * 2 + hi8] - cb;
                if ((sl == 0 || sl == 1) && node < valid_n) {
                    float nh = acc[rd][q];
                    float a  = (nh + Rr) * INV_STEP;
                    int ss   = __float2int_rn(a);
                    ss = max(0, min(31, ss));
                    float sg = fast_sigmoid(ZSTEP * ((float)ss - a));
                    float* d = diff + sl * (NSTEP * HP) + th;
                    atomicAdd(d + ss * HP, sg);
                    if (ss < 31) atomicAdd(d + (ss + 1) * HP, 1.0f - sg);
                }
            }
        }
        __syncthreads();
        if (tid < 64) {                              // flush: 2 slots x 32 theta
            const int sl = tid >> 5, th = tid & 31;
            const int gg = cb + sl;
            if (gg <= gmax) {
                float run = 0.0f;
                const float cnt = (float)cntsh[sl];
                const float* d = diff + sl * (NSTEP * HP) + th;
                float* og = out + (size_t)gg * (NSTEP * NTHETA) + th;
                #pragma unroll 1
                for (int s = 0; s < NSTEP; ++s) {
                    run += d[s * HP];
                    atomicAdd(&og[s * NTHETA], run - cnt * cs_sh[s]);
                }
            }
        }
    }
}

extern "C" void kernel_launch(void* const* d_in, const int* in_sizes, int n_in,
                              void* d_out, int out_size) {
    int xi = 0; long long best = -1;
    for (int i = 0; i < n_in; ++i)
        if ((long long)in_sizes[i] > best) { best = in_sizes[i]; xi = i; }
    const float* x = (const float*)d_in[xi];
    int n_nodes = (int)(best / KFEAT);
    const void* batch = nullptr;
    const float* v = nullptr;
    for (int i = 0; i < n_in; ++i) {
        if (i == xi) continue;
        if (in_sizes[i] == NTHETA * KFEAT) v = (const float*)d_in[i];
        else if (in_sizes[i] == n_nodes)   batch = d_in[i];
    }
    float* out = (float*)d_out;

    static bool attr_set = false;
    if (!attr_set) {
        cudaFuncSetAttribute(ect_hmma_kernel,
                             cudaFuncAttributeMaxDynamicSharedMemorySize, SM_TOTAL);
        attr_set = true;
    }
    zero_kernel<<<(out_size + 255) / 256, 256>>>(out, out_size);
    int tiles = (n_nodes + TILE_N - 1) / TILE_N;
    ect_hmma_kernel<<<tiles, NTHREADS, SM_TOTAL>>>(x, batch, v, out, n_nodes);
}

// round 15
// speedup vs baseline: 1.3921x; 1.3415x over previous
#include <cuda_runtime.h>
#include <cuda_bf16.h>
#include <cstdint>

// Problem constants (fixed by the reference)
#define KFEAT   128
#define NTHETA  32
#define NSTEP   32
#define TILE_N  256      // nodes per CTA (4 x 64-node rounds)
#define RN      64       // nodes per round
#define NROUND  4
#define NTHREADS 256
#define HP      33       // diff-array pitch (bank spread)

// ---- SMEM layout (bytes, dynamic) ----
// bf16 tiles at 256B row pitch, XOR swizzle on 16B seg index: s ^= (row & 7)
#define SA_HI     0          // 64 x 128 bf16 (16 KB)
#define SA_LO     16384
#define SB_HI     32768      // 32 x 128 bf16 (8 KB)
#define SB_LO     40960
#define SM_DIFF   49152      // 2 slots x 32*33 floats (8448 B)
#define SM_BSH    57600      // 256 int
#define SM_BASE   58624      // 2 x 32 int (256 B)
#define SM_CS     58880      // 32 float
#define SM_CNT    59008      // 2 int
#define SM_TOTAL  59016

__device__ __forceinline__ float fast_sigmoid(float z) {
    float e = __expf(-z);
    return __fdividef(1.0f, 1.0f + e);
}

union BU { __nv_bfloat162 h; unsigned u; };

__device__ __forceinline__ unsigned pack_hi(float a, float b, float& ra, float& rb) {
    BU u; u.h = __floats2bfloat162_rn(a, b);
    float2 f = __bfloat1622float2(u.h);
    ra = a - f.x; rb = b - f.y;
    return u.u;
}
__device__ __forceinline__ unsigned pack_lo(float a, float b) {
    BU u; u.h = __floats2bfloat162_rn(a, b); return u.u;
}

__device__ __forceinline__ void ldsm4(unsigned* r, uint32_t addr) {
    asm volatile("ldmatrix.sync.aligned.m8n8.x4.shared.b16 {%0,%1,%2,%3}, [%4];"
        : "=r"(r[0]), "=r"(r[1]), "=r"(r[2]), "=r"(r[3]) : "r"(addr));
}

static __device__ __forceinline__ uint32_t smem_u32(const void* p) {
    uint32_t a;
    asm("{ .reg .u64 t; cvta.to.shared.u64 t, %1; cvt.u32.u64 %0, t; }" : "=r"(a) : "l"(p));
    return a;
}

// D(m16n8) += A(m16k16,row) * B(k16n8,col) ; bf16 in, f32 acc
#define MMA(d0, d1, d2, d3, A, B0, B1) \
    asm volatile("mma.sync.aligned.m16n8k16.row.col.f32.bf16.bf16.f32 " \
        "{%0,%1,%2,%3}, {%4,%5,%6,%7}, {%8,%9}, {%0,%1,%2,%3};" \
        : "+f"(d0), "+f"(d1), "+f"(d2), "+f"(d3) \
        : "r"((A)[0]), "r"((A)[1]), "r"((A)[2]), "r"((A)[3]), "r"(B0), "r"(B1))

__global__ void zero_kernel(float* __restrict__ out, int n) {
    int i = blockIdx.x * blockDim.x + threadIdx.x;
    if (i < n) out[i] = 0.0f;
}

__global__ void __launch_bounds__(NTHREADS, 3)
ect_hmma_kernel(const float* __restrict__ x,
                const void*  __restrict__ batch_raw,
                const float* __restrict__ v,
                float* __restrict__ out,
                int n_nodes)
{
    extern __shared__ char smem[];
    const uint32_t sbase = smem_u32(smem);
    const int tid  = threadIdx.x;
    const int warp = tid >> 5;
    const int lane = tid & 31;
    const int g    = lane >> 2;     // fragment row group
    const int t4   = lane & 3;      // fragment col group
    const int w4   = warp & 3;      // row-slice of the 64-node round
    const int half = warp >> 2;     // theta half: 0 -> th 0-15, 1 -> th 16-31
    const int tile_base = blockIdx.x * TILE_N;
    const int valid_n = min(TILE_N, n_nodes - tile_base);

    float* diff   = (float*)(smem + SM_DIFF);   // [2][NSTEP*HP]
    int*   bsh    = (int*)  (smem + SM_BSH);
    int*   base_i = (int*)  (smem + SM_BASE);   // [2][NTHETA]
    float* cs_sh  = (float*)(smem + SM_CS);
    int*   cntsh  = (int*)  (smem + SM_CNT);

    const float Rr = 1.1f, STEP = 2.2f / 31.0f, INV_STEP = 31.0f / 2.2f;
    const float SCALE = 100.0f;
    const float ZSTEP = SCALE * STEP;   // z-spacing between samples = 7.0968

    // batch dtype: int64 (JAX x64) vs int32 (default)
    const unsigned* bw = (const unsigned*)batch_raw;
    const bool is64 = (bw[n_nodes - 1] == 0u);

    // ---- Stage v -> B_hi/B_lo bf16 (32 rows x 256B): 512 segs, 2/thread ----
    #pragma unroll
    for (int it = 0; it < 2; ++it) {
        int idx = it * NTHREADS + tid;
        int row = idx >> 4, s = idx & 15;
        const float4* p = (const float4*)(v + row * KFEAT + s * 8);
        float4 fa = p[0], fb = p[1];
        float r0, r1, r2, r3, r4, r5, r6, r7;
        uint4 H, L;
        H.x = pack_hi(fa.x, fa.y, r0, r1); H.y = pack_hi(fa.z, fa.w, r2, r3);
        H.z = pack_hi(fb.x, fb.y, r4, r5); H.w = pack_hi(fb.z, fb.w, r6, r7);
        L.x = pack_lo(r0, r1); L.y = pack_lo(r2, r3);
        L.z = pack_lo(r4, r5); L.w = pack_lo(r6, r7);
        int sw = row * 256 + (s ^ (row & 7)) * 16;
        *(uint4*)(smem + SB_HI + sw) = H;
        *(uint4*)(smem + SB_LO + sw) = L;
    }
    // batch labels + pad-sigmoid table
    {
        int n = tile_base + tid;
        int b = 0x7fffffff;
        if (n < n_nodes)
            b = is64 ? (int)((const long long*)batch_raw)[n] : ((const int*)batch_raw)[n];
        bsh[tid] = b;
    }
    if (tid < NSTEP) {
        float lin = fmaf((float)tid, STEP, -Rr);
        float zc  = SCALE * (lin - Rr);
        cs_sh[tid] = (zc > -25.0f) ? fast_sigmoid(zc) : 0.0f;
    }

    // ldmatrix per-lane row bases; swizzled seg index per k-chunk:
    //   addr = rowbase + (((kc*2 + h16) ^ (row&7)) << 4)
    const int l15 = lane & 15, h16 = lane >> 4;
    const int m7 = l15 & 7;
    const uint32_t rowA = sbase + (uint32_t)((w4 * 16 + l15) * 256);
    const uint32_t rowB = sbase + (uint32_t)((half * 16 + l15) * 256);

    float acc[NROUND][8];
    #pragma unroll
    for (int i = 0; i < NROUND; ++i)
        #pragma unroll
        for (int j = 0; j < 8; ++j) acc[i][j] = 0.0f;

    // ---- Four rounds: stage 64 nodes to bf16 hi/lo, HMMA accumulate ----
    #pragma unroll 1
    for (int rd = 0; rd < NROUND; ++rd) {
        __syncthreads();                  // prev round ldsm done / init staging done
        #pragma unroll
        for (int it = 0; it < 4; ++it) {  // 1024 segs, 4/thread
            int idx = it * NTHREADS + tid;
            int row = idx >> 4, s = idx & 15;
            int n = tile_base + rd * RN + row;
            if (n >= n_nodes) n = n_nodes - 1;
            const float4* p = (const float4*)(x + (size_t)n * KFEAT + s * 8);
            float4 fa = p[0], fb = p[1];
            float r0, r1, r2, r3, r4, r5, r6, r7;
            uint4 H, L;
            H.x = pack_hi(fa.x, fa.y, r0, r1); H.y = pack_hi(fa.z, fa.w, r2, r3);
            H.z = pack_hi(fb.x, fb.y, r4, r5); H.w = pack_hi(fb.z, fb.w, r6, r7);
            L.x = pack_lo(r0, r1); L.y = pack_lo(r2, r3);
            L.z = pack_lo(r4, r5); L.w = pack_lo(r6, r7);
            int sw = row * 256 + (s ^ (row & 7)) * 16;
            *(uint4*)(smem + SA_HI + sw) = H;
            *(uint4*)(smem + SA_LO + sw) = L;
        }
        __syncthreads();

        #pragma unroll
        for (int kc = 0; kc < 8; ++kc) {
            const uint32_t so = (uint32_t)(((kc * 2 + h16) ^ m7) << 4);
            unsigned ah[4], al[4], bh[4], bl[4];
            ldsm4(ah, rowA + SA_HI + so);
            ldsm4(al, rowA + SA_LO + so);
            ldsm4(bh, rowB + SB_HI + so);
            ldsm4(bl, rowB + SB_LO + so);
            #pragma unroll
            for (int nb = 0; nb < 2; ++nb) {
                unsigned b0h = bh[nb], b1h = bh[nb + 2];
                unsigned b0l = bl[nb], b1l = bl[nb + 2];
                int j0 = nb * 4;
                MMA(acc[rd][j0], acc[rd][j0+1], acc[rd][j0+2], acc[rd][j0+3], ah, b0h, b1h);
                MMA(acc[rd][j0], acc[rd][j0+1], acc[rd][j0+2], acc[rd][j0+3], ah, b0l, b1l);
                MMA(acc[rd][j0], acc[rd][j0+1], acc[rd][j0+2], acc[rd][j0+3], al, b0h, b1h);
            }
        }
    }

    // Ownership: acc[rd][nb*4+c] = nh[node][theta]
    //   node  = rd*64 + w4*16 + g + (c>=2 ? 8 : 0)
    //   theta = half*16 + nb*8 + 2*t4 + (c&1)
    const int node_base = w4 * 16 + g;
    const unsigned tmask = 0x11111111u << t4;

    // Per-thread node labels for the 8 distinct nodes (rd x c-half)
    int lab8[8];
    #pragma unroll
    for (int rd = 0; rd < NROUND; ++rd) {
        lab8[rd * 2 + 0] = bsh[rd * RN + node_base];
        lab8[rd * 2 + 1] = bsh[rd * RN + node_base + 8];
    }

    // ---- Single-pass two-slot epilogue (R12 atomic policy) ----
    // Per (node,th) with a = (nh+R)/STEP, ss = round(a):
    //   ss <  0  : counts 1 at every s  -> ballot-aggregated per slot (no atomic)
    //   0..31    : +sig at d[sl][ss][th], +(1-sig) at d[sl][ss+1][th] (drop at 31)
    //   ss > 31  : nothing
    // out[g][s][th] = base + prefix_s(d) - cnt_g * cs[s], REDG-merged.
    const int g0   = bsh[0];
    const int gmax = bsh[valid_n - 1];
    #pragma unroll 1
    for (int cb = g0; cb <= gmax; cb += 2) {       // 1 iteration in practice
        __syncthreads();
        for (int i2 = tid; i2 < 2 * NSTEP * HP; i2 += NTHREADS) diff[i2] = 0.0f;
        if (tid < 64) base_i[tid] = 0;
        if (tid >= 64 && tid < 66) cntsh[tid - 64] = 0;
        __syncthreads();
        if (tid < valid_n) {
            int sl = bsh[tid] - cb;
            if (sl == 0 || sl == 1) atomicAdd(&cntsh[sl], 1);
        }

        int basec0[8], basec1[8];
        #pragma unroll
        for (int j = 0; j < 8; ++j) { basec0[j] = 0; basec1[j] = 0; }

        #pragma unroll
        for (int rd = 0; rd < NROUND; ++rd) {
            #pragma unroll
            for (int q = 0; q < 8; ++q) {
                const int nb = q >> 2, c = q & 3;
                const int hi8 = (c >= 2) ? 1 : 0;
                const int node = rd * RN + node_base + hi8 * 8;
                const int th = half * 16 + nb * 8 + 2 * t4 + (c & 1);
                const int sl = lab8[rd * 2 + hi8] - cb;
                const bool inb = ((sl == 0) || (sl == 1)) && (node < valid_n);
                float nh = acc[rd][q];
                float a  = (nh + Rr) * INV_STEP;
                int ss   = __float2int_rn(a);
                const bool isbase = inb && (ss < 0);
                unsigned bal0 = __ballot_sync(0xffffffffu, isbase && (sl == 0));
                unsigned bal1 = __ballot_sync(0xffffffffu, isbase && (sl == 1));
                basec0[q] += __popc(bal0 & tmask);
                basec1[q] += __popc(bal1 & tmask);
                if (inb && ss >= 0 && ss <= 31) {
                    float sg = fast_sigmoid(ZSTEP * ((float)ss - a));
                    float* d = diff + sl * (NSTEP * HP) + th;
                    atomicAdd(d + ss * HP, sg);
                    if (ss < 31) atomicAdd(d + (ss + 1) * HP, 1.0f - sg);
                }
            }
        }
        // lanes 0..3 are the t4==lane leaders; c and c+2 share theta -> sum.
        if (lane < 4) {
            #pragma unroll
            for (int nb = 0; nb < 2; ++nb)
                #pragma unroll
                for (int b01 = 0; b01 < 2; ++b01) {
                    const int th = half * 16 + nb * 8 + 2 * lane + b01;
                    atomicAdd(&base_i[th],
                              basec0[nb * 4 + b01] + basec0[nb * 4 + 2 + b01]);
                    atomicAdd(&base_i[NTHETA + th],
                              basec1[nb * 4 + b01] + basec1[nb * 4 + 2 + b01]);
                }
        }
        __syncthreads();

        if (tid < 64) {                              // flush: 2 slots x 32 theta
            const int sl = tid >> 5, th = tid & 31;
            const int gg = cb + sl;
            if (gg <= gmax) {
                float run = (float)base_i[sl * NTHETA + th];
                const float cnt = (float)cntsh[sl];
                const float* d = diff + sl * (NSTEP * HP) + th;
                float* og = out + (size_t)gg * (NSTEP * NTHETA) + th;
                #pragma unroll 1
                for (int s = 0; s < NSTEP; ++s) {
                    run += d[s * HP];
                    atomicAdd(&og[s * NTHETA], run - cnt * cs_sh[s]);
                }
            }
        }
    }
}

extern "C" void kernel_launch(void* const* d_in, const int* in_sizes, int n_in,
                              void* d_out, int out_size) {
    int xi = 0; long long best = -1;
    for (int i = 0; i < n_in; ++i)
        if ((long long)in_sizes[i] > best) { best = in_sizes[i]; xi = i; }
    const float* x = (const float*)d_in[xi];
    int n_nodes = (int)(best / KFEAT);
    const void* batch = nullptr;
    const float* v = nullptr;
    for (int i = 0; i < n_in; ++i) {
        if (i == xi) continue;
        if (in_sizes[i] == NTHETA * KFEAT) v = (const float*)d_in[i];
        else if (in_sizes[i] == n_nodes)   batch = d_in[i];
    }
    float* out = (float*)d_out;

    static bool attr_set = false;
    if (!attr_set) {
        cudaFuncSetAttribute(ect_hmma_kernel,
                             cudaFuncAttributeMaxDynamicSharedMemorySize, SM_TOTAL);
        attr_set = true;
    }
    zero_kernel<<<(out_size + 255) / 256, 256>>>(out, out_size);
    int tiles = (n_nodes + TILE_N - 1) / TILE_N;
    ect_hmma_kernel<<<tiles, NTHREADS, SM_TOTAL>>>(x, batch, v, out, n_nodes);
}

// round 16
// speedup vs baseline: 1.5262x; 1.0963x over previous
#include <cuda_runtime.h>
#include <cuda_bf16.h>
#include <cstdint>

// Problem constants (fixed by the reference)
#define KFEAT   128
#define NTHETA  32
#define NSTEP   32
#define TILE_N  256      // nodes per CTA (4 x 64-node rounds)
#define RN      64       // nodes per round
#define NROUND  4
#define NTHREADS 256
#define HP      33       // diff-array pitch (bank spread)

// ---- SMEM layout (bytes, dynamic) ----
// bf16 tiles at 256B row pitch, XOR swizzle on 16B seg index: s ^= (row & 7)
#define SA_HI     0          // 64 x 128 bf16 (16 KB)
#define SB_HI     16384      // 32 x 128 bf16 (8 KB)
#define SB_LO     24576      // 8 KB
#define SM_DIFF   32768      // 2 slots x 32*33 floats (8448 B)
#define SM_BSH    41216      // 256 int
#define SM_BASE   42240      // 2 x 32 int (256 B)
#define SM_CS     42496      // 32 float
#define SM_CNT    42624      // 2 int
#define SM_TOTAL  42632

__device__ __forceinline__ float fast_sigmoid(float z) {
    float e = __expf(-z);
    return __fdividef(1.0f, 1.0f + e);
}

union BU { __nv_bfloat162 h; unsigned u; };

__device__ __forceinline__ unsigned pack_hi(float a, float b, float& ra, float& rb) {
    BU u; u.h = __floats2bfloat162_rn(a, b);
    float2 f = __bfloat1622float2(u.h);
    ra = a - f.x; rb = b - f.y;
    return u.u;
}
__device__ __forceinline__ unsigned pack_bf(float a, float b) {
    BU u; u.h = __floats2bfloat162_rn(a, b); return u.u;
}

__device__ __forceinline__ void ldsm4(unsigned* r, uint32_t addr) {
    asm volatile("ldmatrix.sync.aligned.m8n8.x4.shared.b16 {%0,%1,%2,%3}, [%4];"
        : "=r"(r[0]), "=r"(r[1]), "=r"(r[2]), "=r"(r[3]) : "r"(addr));
}

static __device__ __forceinline__ uint32_t smem_u32(const void* p) {
    uint32_t a;
    asm("{ .reg .u64 t; cvta.to.shared.u64 t, %1; cvt.u32.u64 %0, t; }" : "=r"(a) : "l"(p));
    return a;
}

// D(m16n8) += A(m16k16,row) * B(k16n8,col) ; bf16 in, f32 acc
#define MMA(d0, d1, d2, d3, A, B0, B1) \
    asm volatile("mma.sync.aligned.m16n8k16.row.col.f32.bf16.bf16.f32 " \
        "{%0,%1,%2,%3}, {%4,%5,%6,%7}, {%8,%9}, {%0,%1,%2,%3};" \
        : "+f"(d0), "+f"(d1), "+f"(d2), "+f"(d3) \
        : "r"((A)[0]), "r"((A)[1]), "r"((A)[2]), "r"((A)[3]), "r"(B0), "r"(B1))

__global__ void zero_kernel(float* __restrict__ out, int n) {
    int i = blockIdx.x * blockDim.x + threadIdx.x;
    if (i < n) out[i] = 0.0f;
}

__global__ void __launch_bounds__(NTHREADS, 3)
ect_hmma_kernel(const float* __restrict__ x,
                const void*  __restrict__ batch_raw,
                const float* __restrict__ v,
                float* __restrict__ out,
                int n_nodes)
{
    extern __shared__ char smem[];
    const uint32_t sbase = smem_u32(smem);
    const int tid  = threadIdx.x;
    const int warp = tid >> 5;
    const int lane = tid & 31;
    const int g    = lane >> 2;     // fragment row group
    const int t4   = lane & 3;      // fragment col group
    const int w4   = warp & 3;      // row-slice of the 64-node round
    const int half = warp >> 2;     // theta half: 0 -> th 0-15, 1 -> th 16-31
    const int tile_base = blockIdx.x * TILE_N;
    const int valid_n = min(TILE_N, n_nodes - tile_base);

    float* diff   = (float*)(smem + SM_DIFF);   // [2][NSTEP*HP]
    int*   bsh    = (int*)  (smem + SM_BSH);
    int*   base_i = (int*)  (smem + SM_BASE);   // [2][NTHETA]
    float* cs_sh  = (float*)(smem + SM_CS);
    int*   cntsh  = (int*)  (smem + SM_CNT);

    const float Rr = 1.1f, STEP = 2.2f / 31.0f, INV_STEP = 31.0f / 2.2f;
    const float SCALE = 100.0f;
    const float ZSTEP = SCALE * STEP;   // z-spacing between samples = 7.0968

    // batch dtype: int64 (JAX x64) vs int32 (default)
    const unsigned* bw = (const unsigned*)batch_raw;
    const bool is64 = (bw[n_nodes - 1] == 0u);

    // ---- Stage v -> B_hi/B_lo bf16 (32 rows x 256B): 512 segs, 2/thread ----
    // v keeps the 2-way split (B_LO staged once, reused for all tiles' MMAs);
    // x is bf16-rounded only: nh = x_hi*(v_hi+v_lo), residual x_lo*v dropped
    // (~3.3e-3 RMS in nh, same order as the accepted snap error).
    #pragma unroll
    for (int it = 0; it < 2; ++it) {
        int idx = it * NTHREADS + tid;
        int row = idx >> 4, s = idx & 15;
        const float4* p = (const float4*)(v + row * KFEAT + s * 8);
        float4 fa = p[0], fb = p[1];
        float r0, r1, r2, r3, r4, r5, r6, r7;
        uint4 H, L;
        H.x = pack_hi(fa.x, fa.y, r0, r1); H.y = pack_hi(fa.z, fa.w, r2, r3);
        H.z = pack_hi(fb.x, fb.y, r4, r5); H.w = pack_hi(fb.z, fb.w, r6, r7);
        L.x = pack_bf(r0, r1); L.y = pack_bf(r2, r3);
        L.z = pack_bf(r4, r5); L.w = pack_bf(r6, r7);
        int sw = row * 256 + (s ^ (row & 7)) * 16;
        *(uint4*)(smem + SB_HI + sw) = H;
        *(uint4*)(smem + SB_LO + sw) = L;
    }
    // batch labels + pad-sigmoid table
    {
        int n = tile_base + tid;
        int b = 0x7fffffff;
        if (n < n_nodes)
            b = is64 ? (int)((const long long*)batch_raw)[n] : ((const int*)batch_raw)[n];
        bsh[tid] = b;
    }
    if (tid < NSTEP) {
        float lin = fmaf((float)tid, STEP, -Rr);
        float zc  = SCALE * (lin - Rr);
        cs_sh[tid] = (zc > -25.0f) ? fast_sigmoid(zc) : 0.0f;
    }

    // ldmatrix per-lane row bases; swizzled seg index per k-chunk:
    //   addr = rowbase + (((kc*2 + h16) ^ (row&7)) << 4)
    const int l15 = lane & 15, h16 = lane >> 4;
    const int m7 = l15 & 7;
    const uint32_t rowA = sbase + (uint32_t)((w4 * 16 + l15) * 256);
    const uint32_t rowB = sbase + (uint32_t)((half * 16 + l15) * 256);

    float acc[NROUND][8];
    #pragma unroll
    for (int i = 0; i < NROUND; ++i)
        #pragma unroll
        for (int j = 0; j < 8; ++j) acc[i][j] = 0.0f;

    // ---- Four rounds: stage 64 nodes to bf16 (hi only), HMMA accumulate ----
    #pragma unroll 1
    for (int rd = 0; rd < NROUND; ++rd) {
        __syncthreads();                  // prev round ldsm done / init staging done
        #pragma unroll
        for (int it = 0; it < 4; ++it) {  // 1024 segs, 4/thread
            int idx = it * NTHREADS + tid;
            int row = idx >> 4, s = idx & 15;
            int n = tile_base + rd * RN + row;
            if (n >= n_nodes) n = n_nodes - 1;
            const float4* p = (const float4*)(x + (size_t)n * KFEAT + s * 8);
            float4 fa = p[0], fb = p[1];
            uint4 H;
            H.x = pack_bf(fa.x, fa.y); H.y = pack_bf(fa.z, fa.w);
            H.z = pack_bf(fb.x, fb.y); H.w = pack_bf(fb.z, fb.w);
            int sw = row * 256 + (s ^ (row & 7)) * 16;
            *(uint4*)(smem + SA_HI + sw) = H;
        }
        __syncthreads();

        #pragma unroll
        for (int kc = 0; kc < 8; ++kc) {
            const uint32_t so = (uint32_t)(((kc * 2 + h16) ^ m7) << 4);
            unsigned ah[4], bh[4], bl[4];
            ldsm4(ah, rowA + SA_HI + so);
            ldsm4(bh, rowB + SB_HI + so);
            ldsm4(bl, rowB + SB_LO + so);
            #pragma unroll
            for (int nb = 0; nb < 2; ++nb) {
                int j0 = nb * 4;
                MMA(acc[rd][j0], acc[rd][j0+1], acc[rd][j0+2], acc[rd][j0+3],
                    ah, bh[nb], bh[nb + 2]);
                MMA(acc[rd][j0], acc[rd][j0+1], acc[rd][j0+2], acc[rd][j0+3],
                    ah, bl[nb], bl[nb + 2]);
            }
        }
    }

    // Ownership: acc[rd][nb*4+c] = nh[node][theta]
    //   node  = rd*64 + w4*16 + g + (c>=2 ? 8 : 0)
    //   theta = half*16 + nb*8 + 2*t4 + (c&1)
    const int node_base = w4 * 16 + g;
    const unsigned tmask = 0x11111111u << t4;

    // Per-thread node labels for the 8 distinct nodes (rd x c-half)
    int lab8[8];
    #pragma unroll
    for (int rd = 0; rd < NROUND; ++rd) {
        lab8[rd * 2 + 0] = bsh[rd * RN + node_base];
        lab8[rd * 2 + 1] = bsh[rd * RN + node_base + 8];
    }

    // ---- Single-pass two-slot epilogue ----
    // Per (node,th) with a = (nh+R)/STEP, ss = round(a):
    //   ss <  0  : counts 1 at every s  -> ballot-aggregated per slot (no atomic)
    //   0..31    : +sig at d[sl][ss][th], +(1-sig) at d[sl][ss+1][th] (drop at 31)
    //   ss > 31  : nothing
    // out[g][s][th] = base + prefix_s(d) - cnt_g * cs[s], REDG-merged.
    const int g0   = bsh[0];
    const int gmax = bsh[valid_n - 1];
    #pragma unroll 1
    for (int cb = g0; cb <= gmax; cb += 2) {       // 1 iteration in practice
        __syncthreads();
        for (int i2 = tid; i2 < 2 * NSTEP * HP; i2 += NTHREADS) diff[i2] = 0.0f;
        if (tid < 64) base_i[tid] = 0;
        if (tid >= 64 && tid < 66) cntsh[tid - 64] = 0;
        __syncthreads();
        if (tid < valid_n) {
            int sl = bsh[tid] - cb;
            if (sl == 0 || sl == 1) atomicAdd(&cntsh[sl], 1);
        }

        int basec0[8], basec1[8];
        #pragma unroll
        for (int j = 0; j < 8; ++j) { basec0[j] = 0; basec1[j] = 0; }

        #pragma unroll
        for (int rd = 0; rd < NROUND; ++rd) {
            #pragma unroll
            for (int q = 0; q < 8; ++q) {
                const int nb = q >> 2, c = q & 3;
                const int hi8 = (c >= 2) ? 1 : 0;
                const int node = rd * RN + node_base + hi8 * 8;
                const int th = half * 16 + nb * 8 + 2 * t4 + (c & 1);
                const int sl = lab8[rd * 2 + hi8] - cb;
                const bool inb = ((sl == 0) || (sl == 1)) && (node < valid_n);
                float nh = acc[rd][q];
                float a  = (nh + Rr) * INV_STEP;
                int ss   = __float2int_rn(a);
                const bool isbase = inb && (ss < 0);
                unsigned bal0 = __ballot_sync(0xffffffffu, isbase && (sl == 0));
                unsigned bal1 = __ballot_sync(0xffffffffu, isbase && (sl == 1));
                basec0[q] += __popc(bal0 & tmask);
                basec1[q] += __popc(bal1 & tmask);
                if (inb && ss >= 0 && ss <= 31) {
                    float sg = fast_sigmoid(ZSTEP * ((float)ss - a));
                    float* d = diff + sl * (NSTEP * HP) + th;
                    atomicAdd(d + ss * HP, sg);
                    if (ss < 31) atomicAdd(d + (ss + 1) * HP, 1.0f - sg);
                }
            }
        }
        // lanes 0..3 are the t4==lane leaders; c and c+2 share theta -> sum.
        if (lane < 4) {
            #pragma unroll
            for (int nb = 0; nb < 2; ++nb)
                #pragma unroll
                for (int b01 = 0; b01 < 2; ++b01) {
                    const int th = half * 16 + nb * 8 + 2 * lane + b01;
                    atomicAdd(&base_i[th],
                              basec0[nb * 4 + b01] + basec0[nb * 4 + 2 + b01]);
                    atomicAdd(&base_i[NTHETA + th],
                              basec1[nb * 4 + b01] + basec1[nb * 4 + 2 + b01]);
                }
        }
        __syncthreads();

        if (tid < 64) {                              // flush: 2 slots x 32 theta
            const int sl = tid >> 5, th = tid & 31;
            const int gg = cb + sl;
            if (gg <= gmax) {
                float run = (float)base_i[sl * NTHETA + th];
                const float cnt = (float)cntsh[sl];
                const float* d = diff + sl * (NSTEP * HP) + th;
                float* og = out + (size_t)gg * (NSTEP * NTHETA) + th;
                #pragma unroll 1
                for (int s = 0; s < NSTEP; ++s) {
                    run += d[s * HP];
                    atomicAdd(&og[s * NTHETA], run - cnt * cs_sh[s]);
                }
            }
        }
    }
}

extern "C" void kernel_launch(void* const* d_in, const int* in_sizes, int n_in,
                              void* d_out, int out_size) {
    int xi = 0; long long best = -1;
    for (int i = 0; i < n_in; ++i)
        if ((long long)in_sizes[i] > best) { best = in_sizes[i]; xi = i; }
    const float* x = (const float*)d_in[xi];
    int n_nodes = (int)(best / KFEAT);
    const void* batch = nullptr;
    const float* v = nullptr;
    for (int i = 0; i < n_in; ++i) {
        if (i == xi) continue;
        if (in_sizes[i] == NTHETA * KFEAT) v = (const float*)d_in[i];
        else if (in_sizes[i] == n_nodes)   batch = d_in[i];
    }
    float* out = (float*)d_out;

    static bool attr_set = false;
    if (!attr_set) {
        cudaFuncSetAttribute(ect_hmma_kernel,
                             cudaFuncAttributeMaxDynamicSharedMemorySize, SM_TOTAL);
        attr_set = true;
    }
    zero_kernel<<<(out_size + 255) / 256, 256>>>(out, out_size);
    int tiles = (n_nodes + TILE_N - 1) / TILE_N;
    ect_hmma_kernel<<<tiles, NTHREADS, SM_TOTAL>>>(x, batch, v, out, n_nodes);
}